// round 6
// baseline (speedup 1.0000x reference)
#include <cuda_runtime.h>
#include <cstdint>

#define WARPS_PER_BLOCK 8
#define CHUNKS          128   // dim 512 / 4 int4 chunks per row (2KB row)
#define GRID_BLOCKS     512   // single fully-resident wave on 148 SMs

// 16B non-coherent load with 256B L2 fetch granularity: larger DRAM bursts on
// the random row gather (whole 2KB row is consumed, nothing wasted).
__device__ __forceinline__ int4 ldg_nc_256(const int4* p) {
    int4 v;
    asm volatile("ld.global.nc.L2::256B.v4.b32 {%0,%1,%2,%3}, [%4];"
                 : "=r"(v.x), "=r"(v.y), "=r"(v.z), "=r"(v.w)
                 : "l"(p));
    return v;
}

__device__ __forceinline__ void dequant_store(float4* o, int lane,
                                              int4 a0, int4 a1, int4 a2, int4 a3,
                                              float s) {
    __stcs(&o[lane],      make_float4((float)a0.x * s, (float)a0.y * s,
                                      (float)a0.z * s, (float)a0.w * s));
    __stcs(&o[lane + 32], make_float4((float)a1.x * s, (float)a1.y * s,
                                      (float)a1.z * s, (float)a1.w * s));
    __stcs(&o[lane + 64], make_float4((float)a2.x * s, (float)a2.y * s,
                                      (float)a2.z * s, (float)a2.w * s));
    __stcs(&o[lane + 96], make_float4((float)a3.x * s, (float)a3.y * s,
                                      (float)a3.z * s, (float)a3.w * s));
}

// Persistent single-wave kernel: each warp loops over token PAIRS with a
// grid-wide stride. The next iteration's indices+scales are fetched before the
// current iteration's stores, so the idx->gather dependent chain is only paid
// once per warp. Dtype (int64 vs int32) detected inline via ballot over odd
// 32-bit words (little-endian non-negative int64 => all zero).
__global__ __launch_bounds__(WARPS_PER_BLOCK * 32)
void quant_embed_persist_kernel(const unsigned int* __restrict__ x_raw,
                                const int4* __restrict__ w4,
                                const float* __restrict__ scales,
                                float4* __restrict__ out4,
                                int n_tokens)
{
    const int warp_id = threadIdx.x >> 5;
    const int lane    = threadIdx.x & 31;

    // ---- inline dtype detection (uniform across grid) ----
    unsigned probe = 0u;
    {
        int wmax = n_tokens * 2;
        int widx = 2 * lane + 1;
        if (widx < wmax) probe = x_raw[widx];
    }
    const bool is64 = (__ballot_sync(0xFFFFFFFFu, probe != 0u) == 0u);

    const int warp_gid     = blockIdx.x * WARPS_PER_BLOCK + warp_id;
    const int total_warps  = gridDim.x * WARPS_PER_BLOCK;
    const int pair_stride  = total_warps * 2;

    // helper lambda-ish: fetch idx+scale for token pair starting at bt
    auto fetch_pair = [&](int bt, long long& i0, long long& i1,
                          float& s0, float& s1) {
        long long myidx = 0;
        float mys = 0.0f;
        if (lane < 2 && bt + lane < n_tokens) {
            myidx = is64 ? ((const long long*)x_raw)[bt + lane]
                         : (long long)((const int*)x_raw)[bt + lane];
            mys = __ldg(&scales[myidx]);
        }
        i0 = __shfl_sync(0xFFFFFFFFu, myidx, 0);
        i1 = __shfl_sync(0xFFFFFFFFu, myidx, 1);
        s0 = __shfl_sync(0xFFFFFFFFu, mys, 0);
        s1 = __shfl_sync(0xFFFFFFFFu, mys, 1);
    };

    int bt = warp_gid * 2;
    if (bt >= n_tokens) return;

    long long idx0, idx1;
    float s0, s1;
    fetch_pair(bt, idx0, idx1, s0, s1);

    while (true) {
        const bool has1 = (bt + 1) < n_tokens;
        const int4* r0 = w4 + idx0 * CHUNKS;
        const int4* r1 = w4 + idx1 * CHUNKS;

        // issue all row loads back-to-back
        int4 a0 = ldg_nc_256(&r0[lane]);
        int4 a1 = ldg_nc_256(&r0[lane + 32]);
        int4 a2 = ldg_nc_256(&r0[lane + 64]);
        int4 a3 = ldg_nc_256(&r0[lane + 96]);
        int4 b0, b1, b2, b3;
        if (has1) {
            b0 = ldg_nc_256(&r1[lane]);
            b1 = ldg_nc_256(&r1[lane + 32]);
            b2 = ldg_nc_256(&r1[lane + 64]);
            b3 = ldg_nc_256(&r1[lane + 96]);
        }

        // prefetch NEXT pair's indices+scales while row loads are in flight
        const int nbt = bt + pair_stride;
        long long nidx0 = 0, nidx1 = 0;
        float ns0 = 0.0f, ns1 = 0.0f;
        const bool more = nbt < n_tokens;
        if (more) fetch_pair(nbt, nidx0, nidx1, ns0, ns1);

        // dequant + streaming stores
        dequant_store(out4 + (long long)bt * CHUNKS, lane, a0, a1, a2, a3, s0);
        if (has1)
            dequant_store(out4 + (long long)(bt + 1) * CHUNKS, lane,
                          b0, b1, b2, b3, s1);

        if (!more) break;
        bt = nbt;
        idx0 = nidx0; idx1 = nidx1;
        s0 = ns0; s1 = ns1;
    }
}

// Generic fallback for dims other than 512.
__global__ __launch_bounds__(256)
void quant_embed_generic_kernel(const unsigned int* __restrict__ x_raw,
                                const int4* __restrict__ w4,
                                const float* __restrict__ scales,
                                float4* __restrict__ out4,
                                int chunks_per_row, int n_tokens)
{
    const int lane = threadIdx.x & 31;
    unsigned probe = 0u;
    {
        int wmax = n_tokens * 2;
        int widx = 2 * lane + 1;
        if (widx < wmax) probe = x_raw[widx];
    }
    const bool is64 = (__ballot_sync(0xFFFFFFFFu, probe != 0u) == 0u);

    const int warps_per_block = blockDim.x >> 5;
    const int token = blockIdx.x * warps_per_block + (threadIdx.x >> 5);
    if (token >= n_tokens) return;
    long long idx = is64 ? ((const long long*)x_raw)[token]
                         : (long long)((const int*)x_raw)[token];
    float s = __ldg(&scales[idx]);
    const int4* wrow = w4 + idx * chunks_per_row;
    float4* orow = out4 + (long long)token * chunks_per_row;
    for (int c = lane; c < chunks_per_row; c += 32) {
        int4 w = __ldg(&wrow[c]);
        __stcs(&orow[c], make_float4((float)w.x * s, (float)w.y * s,
                                     (float)w.z * s, (float)w.w * s));
    }
}

extern "C" void kernel_launch(void* const* d_in, const int* in_sizes, int n_in,
                              void* d_out, int out_size) {
    const unsigned int* x      = (const unsigned int*)d_in[0];
    const int4*         w4     = (const int4*)d_in[1];
    const float*        scales = (const float*)d_in[2];
    float4*             out4   = (float4*)d_out;

    const int n_tokens = in_sizes[0];
    const int dim      = out_size / n_tokens;   // 512
    const int chunks   = dim / 4;               // 128

    if (chunks == CHUNKS) {
        int pairs = (n_tokens + 1) / 2;
        int blocks_needed = (pairs + WARPS_PER_BLOCK - 1) / WARPS_PER_BLOCK;
        int blocks = blocks_needed < GRID_BLOCKS ? blocks_needed : GRID_BLOCKS;
        quant_embed_persist_kernel<<<blocks, WARPS_PER_BLOCK * 32>>>(
            x, w4, scales, out4, n_tokens);
    } else {
        const int threads = 256;
        const int wpb = threads / 32;
        const int blocks = (n_tokens + wpb - 1) / wpb;
        quant_embed_generic_kernel<<<blocks, threads>>>(x, w4, scales, out4,
                                                        chunks, n_tokens);
    }
}

// round 7
// speedup vs baseline: 1.0382x; 1.0382x over previous
#include <cuda_runtime.h>
#include <cstdint>

#define WARPS_PER_BLOCK 4     // 128-thread blocks: finer scheduling granularity,
                              // more resident warps at 46 regs/thread
#define TOK_PER_WARP    2
#define CHUNKS          128   // dim 512 / 4 int4 chunks per row (2KB row)

// 16B non-coherent load with 256B L2 fetch granularity: each L2 miss pulls
// 256B instead of a 128B sector -> larger DRAM bursts on the random row
// gather (whole 2KB row is consumed, nothing wasted).
__device__ __forceinline__ int4 ldg_nc_256(const int4* p) {
    int4 v;
    asm volatile("ld.global.nc.L2::256B.v4.b32 {%0,%1,%2,%3}, [%4];"
                 : "=r"(v.x), "=r"(v.y), "=r"(v.z), "=r"(v.w)
                 : "l"(p));
    return v;
}

// One warp per 2 tokens. All 8 row loads (+2 scale loads) issued before any
// consume -> high MLP on the DRAM-critical gather. Indices/scales are
// warp-broadcast. Dtype (int64 vs int32) detected inline via ballot over odd
// 32-bit words (little-endian non-negative int64 => all zero).
__global__ __launch_bounds__(WARPS_PER_BLOCK * 32)
void quant_embed_mlp_kernel(const unsigned int* __restrict__ x_raw,
                            const int4* __restrict__ w4,
                            const float* __restrict__ scales,
                            float4* __restrict__ out4,
                            int n_tokens)
{
    const int warp_id = threadIdx.x >> 5;
    const int lane    = threadIdx.x & 31;

    // ---- inline dtype detection (uniform result across grid) ----
    unsigned probe = 0u;
    {
        int wmax = n_tokens * 2;          // words available if int64
        int widx = 2 * lane + 1;
        if (widx < wmax) probe = x_raw[widx];
    }
    const bool is64 = (__ballot_sync(0xFFFFFFFFu, probe != 0u) == 0u);

    const int base_token = (blockIdx.x * WARPS_PER_BLOCK + warp_id) * TOK_PER_WARP;
    if (base_token >= n_tokens) return;
    const bool has1 = (base_token + 1) < n_tokens;

    // ---- indices (lane 0/1 load, broadcast) ----
    long long myidx = 0;
    if (lane < TOK_PER_WARP && base_token + lane < n_tokens) {
        myidx = is64 ? ((const long long*)x_raw)[base_token + lane]
                     : (long long)((const int*)x_raw)[base_token + lane];
    }
    const long long idx0 = __shfl_sync(0xFFFFFFFFu, myidx, 0);
    const long long idx1 = __shfl_sync(0xFFFFFFFFu, myidx, 1);

    const int4* r0 = w4 + idx0 * CHUNKS;
    const int4* r1 = w4 + idx1 * CHUNKS;

    // ---- issue ALL loads back-to-back (8 row loads + scales) ----
    int4 a0 = ldg_nc_256(&r0[lane]);
    int4 a1 = ldg_nc_256(&r0[lane + 32]);
    int4 a2 = ldg_nc_256(&r0[lane + 64]);
    int4 a3 = ldg_nc_256(&r0[lane + 96]);
    int4 b0, b1, b2, b3;
    if (has1) {
        b0 = ldg_nc_256(&r1[lane]);
        b1 = ldg_nc_256(&r1[lane + 32]);
        b2 = ldg_nc_256(&r1[lane + 64]);
        b3 = ldg_nc_256(&r1[lane + 96]);
    }
    const float s0 = __ldg(&scales[idx0]);
    const float s1 = has1 ? __ldg(&scales[idx1]) : 0.0f;

    // ---- dequant + streaming stores (don't pollute L2 with output) ----
    float4* o0 = out4 + (long long)base_token * CHUNKS;
    __stcs(&o0[lane],      make_float4((float)a0.x * s0, (float)a0.y * s0,
                                       (float)a0.z * s0, (float)a0.w * s0));
    __stcs(&o0[lane + 32], make_float4((float)a1.x * s0, (float)a1.y * s0,
                                       (float)a1.z * s0, (float)a1.w * s0));
    __stcs(&o0[lane + 64], make_float4((float)a2.x * s0, (float)a2.y * s0,
                                       (float)a2.z * s0, (float)a2.w * s0));
    __stcs(&o0[lane + 96], make_float4((float)a3.x * s0, (float)a3.y * s0,
                                       (float)a3.z * s0, (float)a3.w * s0));
    if (has1) {
        float4* o1 = out4 + (long long)(base_token + 1) * CHUNKS;
        __stcs(&o1[lane],      make_float4((float)b0.x * s1, (float)b0.y * s1,
                                           (float)b0.z * s1, (float)b0.w * s1));
        __stcs(&o1[lane + 32], make_float4((float)b1.x * s1, (float)b1.y * s1,
                                           (float)b1.z * s1, (float)b1.w * s1));
        __stcs(&o1[lane + 64], make_float4((float)b2.x * s1, (float)b2.y * s1,
                                           (float)b2.z * s1, (float)b2.w * s1));
        __stcs(&o1[lane + 96], make_float4((float)b3.x * s1, (float)b3.y * s1,
                                           (float)b3.z * s1, (float)b3.w * s1));
    }
}

// Generic fallback for dims other than 512.
__global__ __launch_bounds__(256)
void quant_embed_generic_kernel(const unsigned int* __restrict__ x_raw,
                                const int4* __restrict__ w4,
                                const float* __restrict__ scales,
                                float4* __restrict__ out4,
                                int chunks_per_row, int n_tokens)
{
    const int lane = threadIdx.x & 31;
    unsigned probe = 0u;
    {
        int wmax = n_tokens * 2;
        int widx = 2 * lane + 1;
        if (widx < wmax) probe = x_raw[widx];
    }
    const bool is64 = (__ballot_sync(0xFFFFFFFFu, probe != 0u) == 0u);

    const int warps_per_block = blockDim.x >> 5;
    const int token = blockIdx.x * warps_per_block + (threadIdx.x >> 5);
    if (token >= n_tokens) return;
    long long idx = is64 ? ((const long long*)x_raw)[token]
                         : (long long)((const int*)x_raw)[token];
    float s = __ldg(&scales[idx]);
    const int4* wrow = w4 + idx * chunks_per_row;
    float4* orow = out4 + (long long)token * chunks_per_row;
    for (int c = lane; c < chunks_per_row; c += 32) {
        int4 w = __ldg(&wrow[c]);
        __stcs(&orow[c], make_float4((float)w.x * s, (float)w.y * s,
                                     (float)w.z * s, (float)w.w * s));
    }
}

extern "C" void kernel_launch(void* const* d_in, const int* in_sizes, int n_in,
                              void* d_out, int out_size) {
    const unsigned int* x      = (const unsigned int*)d_in[0];
    const int4*         w4     = (const int4*)d_in[1];
    const float*        scales = (const float*)d_in[2];
    float4*             out4   = (float4*)d_out;

    const int n_tokens = in_sizes[0];
    const int dim      = out_size / n_tokens;   // 512
    const int chunks   = dim / 4;               // 128

    if (chunks == CHUNKS) {
        const int tokens_per_block = WARPS_PER_BLOCK * TOK_PER_WARP;  // 8
        const int blocks = (n_tokens + tokens_per_block - 1) / tokens_per_block;
        quant_embed_mlp_kernel<<<blocks, WARPS_PER_BLOCK * 32>>>(
            x, w4, scales, out4, n_tokens);
    } else {
        const int threads = 256;
        const int wpb = threads / 32;
        const int blocks = (n_tokens + wpb - 1) / wpb;
        quant_embed_generic_kernel<<<blocks, threads>>>(x, w4, scales, out4,
                                                        chunks, n_tokens);
    }
}

// round 8
// speedup vs baseline: 1.2179x; 1.1731x over previous
#include <cuda_runtime.h>
#include <cstdint>

#define WARPS_PER_BLOCK 8
#define TOK_PER_WARP    2
#define CHUNKS          128   // dim 512 / 4 int4 chunks per row (2KB row)

// 16B non-coherent load with 256B L2 fetch granularity: each L2 miss pulls
// 256B instead of a 128B sector -> larger DRAM bursts on the random row
// gather (we consume the whole 2KB row, so nothing is wasted).
__device__ __forceinline__ int4 ldg_nc_256(const int4* p) {
    int4 v;
    asm volatile("ld.global.nc.L2::256B.v4.b32 {%0,%1,%2,%3}, [%4];"
                 : "=r"(v.x), "=r"(v.y), "=r"(v.z), "=r"(v.w)
                 : "l"(p));
    return v;
}

// One warp per 2 tokens. All 8 row loads (+2 scale loads) are issued before
// any consume -> ~10 independent loads in flight per thread-chain. Indices /
// scales are warp-broadcast. Dtype (int64 vs int32) detected inline via
// ballot over odd 32-bit words (int64 little-endian non-negative => all 0).
__global__ __launch_bounds__(WARPS_PER_BLOCK * 32)
void quant_embed_mlp_kernel(const unsigned int* __restrict__ x_raw,
                            const int4* __restrict__ w4,
                            const float* __restrict__ scales,
                            float4* __restrict__ out4,
                            int n_tokens)
{
    const int warp_id = threadIdx.x >> 5;
    const int lane    = threadIdx.x & 31;

    // ---- inline dtype detection (uniform result across grid) ----
    unsigned probe = 0u;
    {
        int wmax = n_tokens * 2;          // words available if int64
        int widx = 2 * lane + 1;
        if (widx < wmax) probe = x_raw[widx];
    }
    const bool is64 = (__ballot_sync(0xFFFFFFFFu, probe != 0u) == 0u);

    const int base_token = (blockIdx.x * WARPS_PER_BLOCK + warp_id) * TOK_PER_WARP;
    if (base_token >= n_tokens) return;
    const bool has1 = (base_token + 1) < n_tokens;

    // ---- indices (lane 0/1 load, broadcast) ----
    long long myidx = 0;
    if (lane < TOK_PER_WARP && base_token + lane < n_tokens) {
        myidx = is64 ? ((const long long*)x_raw)[base_token + lane]
                     : (long long)((const int*)x_raw)[base_token + lane];
    }
    const long long idx0 = __shfl_sync(0xFFFFFFFFu, myidx, 0);
    const long long idx1 = __shfl_sync(0xFFFFFFFFu, myidx, 1);

    const int4* r0 = w4 + idx0 * CHUNKS;
    const int4* r1 = w4 + idx1 * CHUNKS;

    // ---- issue ALL loads back-to-back (8 row loads + scales) ----
    int4 a0 = ldg_nc_256(&r0[lane]);
    int4 a1 = ldg_nc_256(&r0[lane + 32]);
    int4 a2 = ldg_nc_256(&r0[lane + 64]);
    int4 a3 = ldg_nc_256(&r0[lane + 96]);
    int4 b0, b1, b2, b3;
    if (has1) {
        b0 = ldg_nc_256(&r1[lane]);
        b1 = ldg_nc_256(&r1[lane + 32]);
        b2 = ldg_nc_256(&r1[lane + 64]);
        b3 = ldg_nc_256(&r1[lane + 96]);
    }
    const float s0 = __ldg(&scales[idx0]);
    const float s1 = has1 ? __ldg(&scales[idx1]) : 0.0f;

    // ---- dequant + streaming stores (don't pollute L2 with output) ----
    float4* o0 = out4 + (long long)base_token * CHUNKS;
    __stcs(&o0[lane],      make_float4((float)a0.x * s0, (float)a0.y * s0,
                                       (float)a0.z * s0, (float)a0.w * s0));
    __stcs(&o0[lane + 32], make_float4((float)a1.x * s0, (float)a1.y * s0,
                                       (float)a1.z * s0, (float)a1.w * s0));
    __stcs(&o0[lane + 64], make_float4((float)a2.x * s0, (float)a2.y * s0,
                                       (float)a2.z * s0, (float)a2.w * s0));
    __stcs(&o0[lane + 96], make_float4((float)a3.x * s0, (float)a3.y * s0,
                                       (float)a3.z * s0, (float)a3.w * s0));
    if (has1) {
        float4* o1 = out4 + (long long)(base_token + 1) * CHUNKS;
        __stcs(&o1[lane],      make_float4((float)b0.x * s1, (float)b0.y * s1,
                                           (float)b0.z * s1, (float)b0.w * s1));
        __stcs(&o1[lane + 32], make_float4((float)b1.x * s1, (float)b1.y * s1,
                                           (float)b1.z * s1, (float)b1.w * s1));
        __stcs(&o1[lane + 64], make_float4((float)b2.x * s1, (float)b2.y * s1,
                                           (float)b2.z * s1, (float)b2.w * s1));
        __stcs(&o1[lane + 96], make_float4((float)b3.x * s1, (float)b3.y * s1,
                                           (float)b3.z * s1, (float)b3.w * s1));
    }
}

// Generic fallback for dims other than 512.
__global__ __launch_bounds__(256)
void quant_embed_generic_kernel(const unsigned int* __restrict__ x_raw,
                                const int4* __restrict__ w4,
                                const float* __restrict__ scales,
                                float4* __restrict__ out4,
                                int chunks_per_row, int n_tokens)
{
    const int lane = threadIdx.x & 31;
    unsigned probe = 0u;
    {
        int wmax = n_tokens * 2;
        int widx = 2 * lane + 1;
        if (widx < wmax) probe = x_raw[widx];
    }
    const bool is64 = (__ballot_sync(0xFFFFFFFFu, probe != 0u) == 0u);

    const int warps_per_block = blockDim.x >> 5;
    const int token = blockIdx.x * warps_per_block + (threadIdx.x >> 5);
    if (token >= n_tokens) return;
    long long idx = is64 ? ((const long long*)x_raw)[token]
                         : (long long)((const int*)x_raw)[token];
    float s = __ldg(&scales[idx]);
    const int4* wrow = w4 + idx * chunks_per_row;
    float4* orow = out4 + (long long)token * chunks_per_row;
    for (int c = lane; c < chunks_per_row; c += 32) {
        int4 w = __ldg(&wrow[c]);
        __stcs(&orow[c], make_float4((float)w.x * s, (float)w.y * s,
                                     (float)w.z * s, (float)w.w * s));
    }
}

extern "C" void kernel_launch(void* const* d_in, const int* in_sizes, int n_in,
                              void* d_out, int out_size) {
    const unsigned int* x      = (const unsigned int*)d_in[0];
    const int4*         w4     = (const int4*)d_in[1];
    const float*        scales = (const float*)d_in[2];
    float4*             out4   = (float4*)d_out;

    const int n_tokens = in_sizes[0];
    const int dim      = out_size / n_tokens;   // 512
    const int chunks   = dim / 4;               // 128

    if (chunks == CHUNKS) {
        const int tokens_per_block = WARPS_PER_BLOCK * TOK_PER_WARP;  // 16
        const int blocks = (n_tokens + tokens_per_block - 1) / tokens_per_block;
        quant_embed_mlp_kernel<<<blocks, WARPS_PER_BLOCK * 32>>>(
            x, w4, scales, out4, n_tokens);
    } else {
        const int threads = 256;
        const int wpb = threads / 32;
        const int blocks = (n_tokens + wpb - 1) / wpb;
        quant_embed_generic_kernel<<<blocks, threads>>>(x, w4, scales, out4,
                                                        chunks, n_tokens);
    }
}